// round 2
// baseline (speedup 1.0000x reference)
#include <cuda_runtime.h>
#include <math_constants.h>

// x: [N=8, C=255, H=128, W=128] fp32.  C = 3 anchors * (5 + 80).
// out: [N=8, 18, H, W]: per (n,a): bx,by,bw,bh,smax,sarg
//
// smax/sarg = max/argmax over the full (n,c) slice per (a,h,w):
//   score[n,a,c,p] = x[n, a*85+5+c, p] * x[n, a*85+4, p]
//   flat index = n*80 + c, first-occurrence argmax, broadcast to all n.

#define NBATCH 8
#define NANCH 3
#define NCLS 80
#define PLANE 16384          // 128*128
#define CH_TOT 255
#define OUT_CH 18

__constant__ float c_anchor_w[NANCH] = {116.0f, 156.0f, 373.0f};
__constant__ float c_anchor_h[NANCH] = {90.0f, 198.0f, 326.0f};

__device__ __forceinline__ float fast_sigmoid(float v) {
    return 1.0f / (1.0f + __expf(-v));
}

// Block: 256 threads = 8 warps. Warp w handles batch n = w for 32 consecutive
// pixels. grid = (PLANE/32, NANCH).
__global__ __launch_bounds__(256, 8)
void anchor_kernel(const float* __restrict__ x, float* __restrict__ out) {
    const int lane = threadIdx.x & 31;
    const int n    = threadIdx.x >> 5;          // 0..7
    const int a    = blockIdx.y;                // 0..2
    const int p    = (blockIdx.x << 5) + lane;  // pixel index 0..16383

    __shared__ float s_max[NBATCH][32];
    __shared__ int   s_idx[NBATCH][32];

    // base pointer for this (n, anchor, pixel); channels stride by PLANE
    const float* base = x + ((size_t)n * CH_TOT + (size_t)a * 85) * PLANE + p;

    const float tx  = base[0 * PLANE];
    const float ty  = base[1 * PLANE];
    const float tw  = base[2 * PLANE];
    const float th  = base[3 * PLANE];
    const float obj = base[4 * PLANE];

    // partial max/argmax over this n's 80 classes, flat idx = n*80 + c
    float m  = -CUDART_INF_F;
    int   mi = n * NCLS;
    const float* cls = base + 5 * PLANE;
#pragma unroll 16
    for (int c = 0; c < NCLS; ++c) {
        const float v = cls[(size_t)c * PLANE] * obj;
        if (v > m) { m = v; mi = n * NCLS + c; }
    }
    s_max[n][lane] = m;
    s_idx[n][lane] = mi;
    __syncthreads();

    // warp 0 combines the 8 partials in ascending-n order (tie-break = first occurrence)
    if (n == 0) {
        float fm  = s_max[0][lane];
        int   fmi = s_idx[0][lane];
#pragma unroll
        for (int k = 1; k < NBATCH; ++k) {
            const float v = s_max[k][lane];
            if (v > fm) { fm = v; fmi = s_idx[k][lane]; }
        }
        s_max[0][lane] = fm;
        s_idx[0][lane] = fmi;
    }
    __syncthreads();

    const float smax = s_max[0][lane];
    const float sarg = (float)s_idx[0][lane];

    const float gx = (float)(p & 127);
    const float gy = (float)(p >> 7);

    const float bx = fast_sigmoid(tx) + gx;
    const float by = fast_sigmoid(ty) + gy;
    const float bw = tw * c_anchor_w[a];
    const float bh = th * c_anchor_h[a];

    float* ob = out + ((size_t)n * OUT_CH + (size_t)a * 6) * PLANE + p;
    ob[0 * PLANE] = bx;
    ob[1 * PLANE] = by;
    ob[2 * PLANE] = bw;
    ob[3 * PLANE] = bh;
    ob[4 * PLANE] = smax;
    ob[5 * PLANE] = sarg;
}

extern "C" void kernel_launch(void* const* d_in, const int* in_sizes, int n_in,
                              void* d_out, int out_size) {
    (void)in_sizes; (void)n_in; (void)out_size;
    const float* x = (const float*)d_in[0];
    float* out = (float*)d_out;
    dim3 grid(PLANE / 32, NANCH);
    anchor_kernel<<<grid, 256>>>(x, out);
}

// round 3
// speedup vs baseline: 1.0010x; 1.0010x over previous
#include <cuda_runtime.h>
#include <math_constants.h>

// x: [N=8, C=255, H=128, W=128] fp32.  C = 3 anchors * (5 + 80).
// out: [N=8, 18, H, W]: per (n,a): bx,by,bw,bh,smax,sarg
//
// smax/sarg = max/argmax over the full (n,c) slice per (a,h,w):
//   score[n,a,c,p] = x[n, a*85+5+c, p] * x[n, a*85+4, p]
//   flat index = n*80 + c, first-occurrence argmax, broadcast to all n.

#define NBATCH 8
#define NANCH 3
#define NCLS 80
#define PLANE 16384          // 128*128
#define CH_TOT 255
#define OUT_CH 18

__constant__ float c_anchor_w[NANCH] = {116.0f, 156.0f, 373.0f};
__constant__ float c_anchor_h[NANCH] = {90.0f, 198.0f, 326.0f};

__device__ __forceinline__ float fast_sigmoid(float v) {
    return 1.0f / (1.0f + __expf(-v));
}

// Block: 256 threads = 8 warps. Warp w handles batch n = w for 32 consecutive
// pixels. grid = (PLANE/32, NANCH).
__global__ __launch_bounds__(256, 8)
void anchor_kernel(const float* __restrict__ x, float* __restrict__ out) {
    const int lane = threadIdx.x & 31;
    const int n    = threadIdx.x >> 5;          // 0..7
    const int a    = blockIdx.y;                // 0..2
    const int p    = (blockIdx.x << 5) + lane;  // pixel index 0..16383

    __shared__ float s_max[NBATCH][32];
    __shared__ int   s_idx[NBATCH][32];

    // base pointer for this (n, anchor, pixel); channels stride by PLANE
    const float* base = x + ((size_t)n * CH_TOT + (size_t)a * 85) * PLANE + p;

    const float tx  = base[0 * PLANE];
    const float ty  = base[1 * PLANE];
    const float tw  = base[2 * PLANE];
    const float th  = base[3 * PLANE];
    const float obj = base[4 * PLANE];

    // partial max/argmax over this n's 80 classes, flat idx = n*80 + c
    float m  = -CUDART_INF_F;
    int   mi = n * NCLS;
    const float* cls = base + 5 * PLANE;
#pragma unroll 16
    for (int c = 0; c < NCLS; ++c) {
        const float v = cls[(size_t)c * PLANE] * obj;
        if (v > m) { m = v; mi = n * NCLS + c; }
    }
    s_max[n][lane] = m;
    s_idx[n][lane] = mi;
    __syncthreads();

    // warp 0 combines the 8 partials in ascending-n order (tie-break = first occurrence)
    if (n == 0) {
        float fm  = s_max[0][lane];
        int   fmi = s_idx[0][lane];
#pragma unroll
        for (int k = 1; k < NBATCH; ++k) {
            const float v = s_max[k][lane];
            if (v > fm) { fm = v; fmi = s_idx[k][lane]; }
        }
        s_max[0][lane] = fm;
        s_idx[0][lane] = fmi;
    }
    __syncthreads();

    const float smax = s_max[0][lane];
    const float sarg = (float)s_idx[0][lane];

    const float gx = (float)(p & 127);
    const float gy = (float)(p >> 7);

    const float bx = fast_sigmoid(tx) + gx;
    const float by = fast_sigmoid(ty) + gy;
    const float bw = tw * c_anchor_w[a];
    const float bh = th * c_anchor_h[a];

    float* ob = out + ((size_t)n * OUT_CH + (size_t)a * 6) * PLANE + p;
    ob[0 * PLANE] = bx;
    ob[1 * PLANE] = by;
    ob[2 * PLANE] = bw;
    ob[3 * PLANE] = bh;
    ob[4 * PLANE] = smax;
    ob[5 * PLANE] = sarg;
}

extern "C" void kernel_launch(void* const* d_in, const int* in_sizes, int n_in,
                              void* d_out, int out_size) {
    (void)in_sizes; (void)n_in; (void)out_size;
    const float* x = (const float*)d_in[0];
    float* out = (float*)d_out;
    dim3 grid(PLANE / 32, NANCH);
    anchor_kernel<<<grid, 256>>>(x, out);
}